// round 14
// baseline (speedup 1.0000x reference)
#include <cuda_runtime.h>

// Problem constants
#define BATCH   2
#define S_LEN   2048
#define EMB     1024
#define NHEAD   16
#define HDIM    64
#define MROWS   (BATCH * S_LEN)          // 4096

// Scratch (allocation-free rule: static __device__ arrays)
__device__ float g_q[BATCH * NHEAD * S_LEN * HDIM];   // [b,h,s,d]
__device__ float g_k[BATCH * NHEAD * S_LEN * HDIM];
__device__ float g_v[BATCH * NHEAD * S_LEN * HDIM];
__device__ float g_att[MROWS * EMB];                  // [b,s,e] e = h*64+d

// ---------------------------------------------------------------------------
// Packed fp32x2 helpers (Blackwell dual fp32 pipe; exact fp32 FMA semantics).
// Controlled experiment: the 128MiB local-arena violations (R5-R9, R11-R12)
// all contained tensor-core instruction paths; this is plain FMA-pipe asm.
// Scalar references only — no address-of-local enters asm.
// ---------------------------------------------------------------------------
typedef unsigned long long u64p;

__device__ __forceinline__ void fma2(u64p& c, u64p a, u64p b) {
    asm("fma.rn.f32x2 %0, %1, %2, %0;" : "+l"(c) : "l"(a), "l"(b));
}
__device__ __forceinline__ u64p pack2(float x, float y) {
    u64p r;
    asm("mov.b64 %0, {%1, %2};" : "=l"(r) : "f"(x), "f"(y));
    return r;
}
__device__ __forceinline__ float2 unpack2(u64p p) {
    float lo, hi;
    asm("mov.b64 {%0, %1}, %2;" : "=f"(lo), "=f"(hi) : "l"(p));
    return make_float2(lo, hi);
}

// ---------------------------------------------------------------------------
// SGEMM via fma.rn.f32x2: C = A @ B^T. 128x128 tile, BK=8, 256 threads,
// 8x8 per thread held as 8x4 packed pairs. R13 measured the scalar-FFMA
// version AT the fp32 roofline (fma pipe 50.2% = saturation at rt_SMSP=2);
// packed math halves FFMA-pipe occupancy per FLOP.
// ---------------------------------------------------------------------------
#define BM 128
#define BN 128
#define BKK 8

__global__ __launch_bounds__(256) void qkv_gemm(
    const float* __restrict__ X,
    const float* __restrict__ Wq,
    const float* __restrict__ Wk,
    const float* __restrict__ Wv)
{
    const int K = EMB;
    const float* W   = (blockIdx.z == 0) ? Wq : (blockIdx.z == 1) ? Wk : Wv;
    float*       Dst = (blockIdx.z == 0) ? g_q : (blockIdx.z == 1) ? g_k : g_v;

    __shared__ __align__(16) float As[BKK][BM];
    __shared__ __align__(16) float Bs[BKK][BN];

    const int tid = threadIdx.x;
    const int m0  = blockIdx.y * BM;
    const int n0  = blockIdx.x * BN;

    const int lrow = tid >> 1;          // 0..127
    const int lcol = (tid & 1) * 4;     // 0 or 4

    const float* Aptr = X + (size_t)(m0 + lrow) * K + lcol;
    const float* Bptr = W + (size_t)(n0 + lrow) * K + lcol;

    u64p acc[8][4];                     // [i][j] = C(i, 2j..2j+1) packed
#pragma unroll
    for (int i = 0; i < 8; i++)
#pragma unroll
        for (int j = 0; j < 4; j++) acc[i][j] = 0ull;

    const int ty = tid >> 4;   // 0..15
    const int tx = tid & 15;   // 0..15

    float4 a_cur = *(const float4*)(Aptr);
    float4 b_cur = *(const float4*)(Bptr);

    for (int k0 = 0; k0 < K; k0 += BKK) {
        As[lcol + 0][lrow] = a_cur.x; As[lcol + 1][lrow] = a_cur.y;
        As[lcol + 2][lrow] = a_cur.z; As[lcol + 3][lrow] = a_cur.w;
        Bs[lcol + 0][lrow] = b_cur.x; Bs[lcol + 1][lrow] = b_cur.y;
        Bs[lcol + 2][lrow] = b_cur.z; Bs[lcol + 3][lrow] = b_cur.w;
        __syncthreads();

        if (k0 + BKK < K) {
            a_cur = *(const float4*)(Aptr + k0 + BKK);
            b_cur = *(const float4*)(Bptr + k0 + BKK);
        }

#pragma unroll
        for (int kk = 0; kk < BKK; kk++) {
            float4 a0 = *(const float4*)&As[kk][ty * 8];
            float4 a1 = *(const float4*)&As[kk][ty * 8 + 4];
            // B pairs read directly as 8-byte packed values (even float idx)
            u64p bp0 = *(const u64p*)&Bs[kk][tx * 8 + 0];
            u64p bp1 = *(const u64p*)&Bs[kk][tx * 8 + 2];
            u64p bp2 = *(const u64p*)&Bs[kk][tx * 8 + 4];
            u64p bp3 = *(const u64p*)&Bs[kk][tx * 8 + 6];
            float ar[8] = {a0.x, a0.y, a0.z, a0.w, a1.x, a1.y, a1.z, a1.w};
#pragma unroll
            for (int i = 0; i < 8; i++) {
                const u64p ap = pack2(ar[i], ar[i]);
                fma2(acc[i][0], ap, bp0);
                fma2(acc[i][1], ap, bp1);
                fma2(acc[i][2], ap, bp2);
                fma2(acc[i][3], ap, bp3);
            }
        }
        __syncthreads();
    }

    // Epilogue: scatter into [b,h,s,d].
#pragma unroll
    for (int i = 0; i < 8; i++) {
        const int m = m0 + ty * 8 + i;
        const int b = m >> 11;          // /2048
        const int s = m & 2047;
#pragma unroll
        for (int j = 0; j < 2; j++) {
            const int n = n0 + tx * 8 + j * 4;
            const int h = n >> 6;
            const int d = n & 63;
            float2 p0 = unpack2(acc[i][j * 2 + 0]);
            float2 p1 = unpack2(acc[i][j * 2 + 1]);
            float4 v = make_float4(p0.x, p0.y, p1.x, p1.y);
            *(float4*)&Dst[((size_t)(b * NHEAD + h) * S_LEN + s) * HDIM + d] = v;
        }
    }
}

__global__ __launch_bounds__(256) void outproj_gemm(
    const float* __restrict__ Wo,
    const float* __restrict__ bo,
    float* __restrict__ Out)
{
    const int K = EMB;
    const float* A = g_att;

    __shared__ __align__(16) float As[BKK][BM];
    __shared__ __align__(16) float Bs[BKK][BN];

    const int tid = threadIdx.x;
    const int m0  = blockIdx.y * BM;
    const int n0  = blockIdx.x * BN;

    const int lrow = tid >> 1;
    const int lcol = (tid & 1) * 4;

    const float* Aptr = A  + (size_t)(m0 + lrow) * K + lcol;
    const float* Bptr = Wo + (size_t)(n0 + lrow) * K + lcol;

    u64p acc[8][4];
#pragma unroll
    for (int i = 0; i < 8; i++)
#pragma unroll
        for (int j = 0; j < 4; j++) acc[i][j] = 0ull;

    const int ty = tid >> 4;
    const int tx = tid & 15;

    float4 a_cur = *(const float4*)(Aptr);
    float4 b_cur = *(const float4*)(Bptr);

    for (int k0 = 0; k0 < K; k0 += BKK) {
        As[lcol + 0][lrow] = a_cur.x; As[lcol + 1][lrow] = a_cur.y;
        As[lcol + 2][lrow] = a_cur.z; As[lcol + 3][lrow] = a_cur.w;
        Bs[lcol + 0][lrow] = b_cur.x; Bs[lcol + 1][lrow] = b_cur.y;
        Bs[lcol + 2][lrow] = b_cur.z; Bs[lcol + 3][lrow] = b_cur.w;
        __syncthreads();

        if (k0 + BKK < K) {
            a_cur = *(const float4*)(Aptr + k0 + BKK);
            b_cur = *(const float4*)(Bptr + k0 + BKK);
        }

#pragma unroll
        for (int kk = 0; kk < BKK; kk++) {
            float4 a0 = *(const float4*)&As[kk][ty * 8];
            float4 a1 = *(const float4*)&As[kk][ty * 8 + 4];
            u64p bp0 = *(const u64p*)&Bs[kk][tx * 8 + 0];
            u64p bp1 = *(const u64p*)&Bs[kk][tx * 8 + 2];
            u64p bp2 = *(const u64p*)&Bs[kk][tx * 8 + 4];
            u64p bp3 = *(const u64p*)&Bs[kk][tx * 8 + 6];
            float ar[8] = {a0.x, a0.y, a0.z, a0.w, a1.x, a1.y, a1.z, a1.w};
#pragma unroll
            for (int i = 0; i < 8; i++) {
                const u64p ap = pack2(ar[i], ar[i]);
                fma2(acc[i][0], ap, bp0);
                fma2(acc[i][1], ap, bp1);
                fma2(acc[i][2], ap, bp2);
                fma2(acc[i][3], ap, bp3);
            }
        }
        __syncthreads();
    }

#pragma unroll
    for (int i = 0; i < 8; i++) {
        const int m = m0 + ty * 8 + i;
#pragma unroll
        for (int j = 0; j < 2; j++) {
            const int n = n0 + tx * 8 + j * 4;
            float2 p0 = unpack2(acc[i][j * 2 + 0]);
            float2 p1 = unpack2(acc[i][j * 2 + 1]);
            float4 bb = *(const float4*)&bo[n];
            float4 v = make_float4(p0.x + bb.x, p0.y + bb.y,
                                   p1.x + bb.z, p1.y + bb.w);
            *(float4*)&Out[(size_t)m * EMB + n] = v;
        }
    }
}

// ---------------------------------------------------------------------------
// Attention (inverted causal mask: attend only strictly-future keys).
// EXACT R13 kernel (double-buffered K/V, passed at ~1005us, delta=0).
// Untouched this round to isolate the f32x2 GEMM experiment.
// ---------------------------------------------------------------------------
#define BQ  128
#define BKV 32

__global__ __launch_bounds__(BQ) void attn_kernel()
{
    const int bh = blockIdx.y;              // b*16 + h
    const int b  = bh >> 4;
    const int h  = bh & 15;
    const int q0 = blockIdx.x * BQ;
    const int t  = threadIdx.x;
    const int qrow = q0 + t;

    const float* Qb = g_q + (size_t)bh * S_LEN * HDIM;
    const float* Kb = g_k + (size_t)bh * S_LEN * HDIM;
    const float* Vb = g_v + (size_t)bh * S_LEN * HDIM;

    __shared__ float Ks[2][BKV * HDIM];     // 2 x 8KB
    __shared__ float Vs[2][BKV * HDIM];     // 2 x 8KB

    float4 q4[16];
    const float4* qp = (const float4*)(Qb + (size_t)qrow * HDIM);
#pragma unroll
    for (int i = 0; i < 16; i++) q4[i] = qp[i];

    float4 acc[16];
#pragma unroll
    for (int i = 0; i < 16; i++) acc[i] = make_float4(0.f, 0.f, 0.f, 0.f);

    float mrun = -1e30f;
    float lrun = 0.f;
    const float sc_qk = 0.125f;             // 1/sqrt(64)

    const int ntiles = S_LEN / BKV;         // 64
    const int tstart = (blockIdx.x == gridDim.x - 1) ? 0 : (q0 / BKV);

    // Prologue: load tile tstart into buffer 0.
    {
        const float* kp = Kb + (size_t)tstart * BKV * HDIM;
        const float* vp = Vb + (size_t)tstart * BKV * HDIM;
        for (int i = t * 4; i < BKV * HDIM; i += BQ * 4) {
            *(float4*)(&Ks[0][i]) = *(const float4*)(kp + i);
            *(float4*)(&Vs[0][i]) = *(const float4*)(vp + i);
        }
    }
    __syncthreads();

    for (int kt = tstart; kt < ntiles; kt++) {
        const int buf = (kt - tstart) & 1;

        if (kt + 1 < ntiles) {
            const float* kp = Kb + (size_t)(kt + 1) * BKV * HDIM;
            const float* vp = Vb + (size_t)(kt + 1) * BKV * HDIM;
            for (int i = t * 4; i < BKV * HDIM; i += BQ * 4) {
                *(float4*)(&Ks[buf ^ 1][i]) = *(const float4*)(kp + i);
                *(float4*)(&Vs[buf ^ 1][i]) = *(const float4*)(vp + i);
            }
        }

#pragma unroll 1
        for (int jc = 0; jc < BKV; jc += 8) {
            float sc[8];
#pragma unroll
            for (int jj = 0; jj < 8; jj++) {
                const float4* kp = (const float4*)(&Ks[buf][(jc + jj) * HDIM]);
                float sum = 0.f;
#pragma unroll
                for (int i = 0; i < 16; i++) {
                    float4 kv = kp[i];
                    sum += q4[i].x * kv.x + q4[i].y * kv.y
                         + q4[i].z * kv.z + q4[i].w * kv.w;
                }
                const int kg = kt * BKV + jc + jj;
                sc[jj] = (kg > qrow) ? sum * sc_qk : -1e9f;
            }
            float cmax = sc[0];
#pragma unroll
            for (int jj = 1; jj < 8; jj++) cmax = fmaxf(cmax, sc[jj]);
            const float mnew = fmaxf(mrun, cmax);
            const float corr = __expf(mrun - mnew);
            lrun *= corr;
#pragma unroll
            for (int i = 0; i < 16; i++) {
                acc[i].x *= corr; acc[i].y *= corr;
                acc[i].z *= corr; acc[i].w *= corr;
            }
#pragma unroll
            for (int jj = 0; jj < 8; jj++) {
                const float p = __expf(sc[jj] - mnew);
                lrun += p;
                const float4* vp = (const float4*)(&Vs[buf][(jc + jj) * HDIM]);
#pragma unroll
                for (int i = 0; i < 16; i++) {
                    float4 vv = vp[i];
                    acc[i].x += p * vv.x; acc[i].y += p * vv.y;
                    acc[i].z += p * vv.z; acc[i].w += p * vv.w;
                }
            }
            mrun = mnew;
        }
        __syncthreads();
    }

    const float inv = 1.f / lrun;
    float* op = g_att + ((size_t)(b * S_LEN + qrow)) * EMB + h * HDIM;
#pragma unroll
    for (int i = 0; i < 16; i++) {
        float4 v = make_float4(acc[i].x * inv, acc[i].y * inv,
                               acc[i].z * inv, acc[i].w * inv);
        ((float4*)op)[i] = v;
    }
}

// ---------------------------------------------------------------------------
extern "C" void kernel_launch(void* const* d_in, const int* in_sizes, int n_in,
                              void* d_out, int out_size)
{
    const float* x  = (const float*)d_in[0];
    const float* wq = (const float*)d_in[1];
    const float* wk = (const float*)d_in[2];
    const float* wv = (const float*)d_in[3];
    const float* wo = (const float*)d_in[4];
    const float* bo = (const float*)d_in[5];
    float* out = (float*)d_out;

    // 1) QKV projections -> g_q/g_k/g_v in [b,h,s,d]
    {
        dim3 grid(EMB / BN, MROWS / BM, 3);
        qkv_gemm<<<grid, 256>>>(x, wq, wk, wv);
    }
    // 2) Attention -> g_att in [b,s,e]
    {
        dim3 grid(S_LEN / BQ, BATCH * NHEAD);
        attn_kernel<<<grid, BQ>>>();
    }
    // 3) Output projection + bias -> d_out
    {
        dim3 grid(EMB / BN, MROWS / BM);
        outproj_gemm<<<grid, 256>>>(wo, bo, out);
    }
}

// round 15
// speedup vs baseline: 1.0254x; 1.0254x over previous
#include <cuda_runtime.h>

// Problem constants
#define BATCH   2
#define S_LEN   2048
#define EMB     1024
#define NHEAD   16
#define HDIM    64
#define MROWS   (BATCH * S_LEN)          // 4096

// Scratch (allocation-free rule: static __device__ arrays)
__device__ float g_q[BATCH * NHEAD * S_LEN * HDIM];   // [b,h,s,d]
__device__ float g_k[BATCH * NHEAD * S_LEN * HDIM];
__device__ float g_v[BATCH * NHEAD * S_LEN * HDIM];
__device__ float g_att[MROWS * EMB];                  // [b,s,e] e = h*64+d

// ---------------------------------------------------------------------------
// Packed fp32x2 helpers. R14 proved: (a) plain-pipe asm does NOT trip the
// 128MiB arena (only tensor-core paths do); (b) f32x2 gives no extra fp32
// FLOP rate (pipe-bound GEMM unchanged) but HALVES issue slots + registers.
// => use scalar FFMA for the pipe-bound GEMMs, f32x2 for the issue/latency-
// bound attention kernel.
// ---------------------------------------------------------------------------
typedef unsigned long long u64p;

__device__ __forceinline__ void fma2(u64p& c, u64p a, u64p b) {
    asm("fma.rn.f32x2 %0, %1, %2, %0;" : "+l"(c) : "l"(a), "l"(b));
}
__device__ __forceinline__ void mul2(u64p& c, u64p a, u64p b) {
    asm("mul.rn.f32x2 %0, %1, %2;" : "=l"(c) : "l"(a), "l"(b));
}
__device__ __forceinline__ u64p pack2(float x, float y) {
    u64p r;
    asm("mov.b64 %0, {%1, %2};" : "=l"(r) : "f"(x), "f"(y));
    return r;
}
__device__ __forceinline__ float2 unpack2(u64p p) {
    float lo, hi;
    asm("mov.b64 {%0, %1}, %2;" : "=f"(lo), "=f"(hi) : "l"(p));
    return make_float2(lo, hi);
}

// ---------------------------------------------------------------------------
// SGEMM (scalar FFMA): C = A @ B^T. 128x128 tile, BK=8, 256 threads,
// 8x8/thread, register prefetch. EXACT R13 kernels — measured AT the fp32
// roofline (fma pipe ~50% = saturation at rt_SMSP=2; f32x2 variant was NOT
// faster because the pipe FLOP rate is identical).
// ---------------------------------------------------------------------------
#define BM 128
#define BN 128
#define BKK 8

__global__ __launch_bounds__(256) void qkv_gemm(
    const float* __restrict__ X,
    const float* __restrict__ Wq,
    const float* __restrict__ Wk,
    const float* __restrict__ Wv)
{
    const int K = EMB;
    const float* W   = (blockIdx.z == 0) ? Wq : (blockIdx.z == 1) ? Wk : Wv;
    float*       Dst = (blockIdx.z == 0) ? g_q : (blockIdx.z == 1) ? g_k : g_v;

    __shared__ float As[BKK][BM];
    __shared__ float Bs[BKK][BN];

    const int tid = threadIdx.x;
    const int m0  = blockIdx.y * BM;
    const int n0  = blockIdx.x * BN;

    const int lrow = tid >> 1;          // 0..127
    const int lcol = (tid & 1) * 4;     // 0 or 4

    const float* Aptr = X + (size_t)(m0 + lrow) * K + lcol;
    const float* Bptr = W + (size_t)(n0 + lrow) * K + lcol;

    float acc[8][8];
#pragma unroll
    for (int i = 0; i < 8; i++)
#pragma unroll
        for (int j = 0; j < 8; j++) acc[i][j] = 0.f;

    const int ty = tid >> 4;   // 0..15
    const int tx = tid & 15;   // 0..15

    float4 a_cur = *(const float4*)(Aptr);
    float4 b_cur = *(const float4*)(Bptr);

    for (int k0 = 0; k0 < K; k0 += BKK) {
        As[lcol + 0][lrow] = a_cur.x; As[lcol + 1][lrow] = a_cur.y;
        As[lcol + 2][lrow] = a_cur.z; As[lcol + 3][lrow] = a_cur.w;
        Bs[lcol + 0][lrow] = b_cur.x; Bs[lcol + 1][lrow] = b_cur.y;
        Bs[lcol + 2][lrow] = b_cur.z; Bs[lcol + 3][lrow] = b_cur.w;
        __syncthreads();

        if (k0 + BKK < K) {
            a_cur = *(const float4*)(Aptr + k0 + BKK);
            b_cur = *(const float4*)(Bptr + k0 + BKK);
        }

#pragma unroll
        for (int kk = 0; kk < BKK; kk++) {
            float4 a0 = *(const float4*)&As[kk][ty * 8];
            float4 a1 = *(const float4*)&As[kk][ty * 8 + 4];
            float4 b0 = *(const float4*)&Bs[kk][tx * 8];
            float4 b1 = *(const float4*)&Bs[kk][tx * 8 + 4];
            float ar[8] = {a0.x, a0.y, a0.z, a0.w, a1.x, a1.y, a1.z, a1.w};
            float br[8] = {b0.x, b0.y, b0.z, b0.w, b1.x, b1.y, b1.z, b1.w};
#pragma unroll
            for (int i = 0; i < 8; i++)
#pragma unroll
                for (int j = 0; j < 8; j++) acc[i][j] += ar[i] * br[j];
        }
        __syncthreads();
    }

#pragma unroll
    for (int i = 0; i < 8; i++) {
        const int m = m0 + ty * 8 + i;
        const int b = m >> 11;          // /2048
        const int s = m & 2047;
#pragma unroll
        for (int j = 0; j < 8; j += 4) {
            const int n = n0 + tx * 8 + j;
            const int h = n >> 6;
            const int d = n & 63;
            float4 v = make_float4(acc[i][j], acc[i][j+1], acc[i][j+2], acc[i][j+3]);
            *(float4*)&Dst[((size_t)(b * NHEAD + h) * S_LEN + s) * HDIM + d] = v;
        }
    }
}

__global__ __launch_bounds__(256) void outproj_gemm(
    const float* __restrict__ Wo,
    const float* __restrict__ bo,
    float* __restrict__ Out)
{
    const int K = EMB;
    const float* A = g_att;

    __shared__ float As[BKK][BM];
    __shared__ float Bs[BKK][BN];

    const int tid = threadIdx.x;
    const int m0  = blockIdx.y * BM;
    const int n0  = blockIdx.x * BN;

    const int lrow = tid >> 1;
    const int lcol = (tid & 1) * 4;

    const float* Aptr = A  + (size_t)(m0 + lrow) * K + lcol;
    const float* Bptr = Wo + (size_t)(n0 + lrow) * K + lcol;

    float acc[8][8];
#pragma unroll
    for (int i = 0; i < 8; i++)
#pragma unroll
        for (int j = 0; j < 8; j++) acc[i][j] = 0.f;

    const int ty = tid >> 4;
    const int tx = tid & 15;

    float4 a_cur = *(const float4*)(Aptr);
    float4 b_cur = *(const float4*)(Bptr);

    for (int k0 = 0; k0 < K; k0 += BKK) {
        As[lcol + 0][lrow] = a_cur.x; As[lcol + 1][lrow] = a_cur.y;
        As[lcol + 2][lrow] = a_cur.z; As[lcol + 3][lrow] = a_cur.w;
        Bs[lcol + 0][lrow] = b_cur.x; Bs[lcol + 1][lrow] = b_cur.y;
        Bs[lcol + 2][lrow] = b_cur.z; Bs[lcol + 3][lrow] = b_cur.w;
        __syncthreads();

        if (k0 + BKK < K) {
            a_cur = *(const float4*)(Aptr + k0 + BKK);
            b_cur = *(const float4*)(Bptr + k0 + BKK);
        }

#pragma unroll
        for (int kk = 0; kk < BKK; kk++) {
            float4 a0 = *(const float4*)&As[kk][ty * 8];
            float4 a1 = *(const float4*)&As[kk][ty * 8 + 4];
            float4 b0 = *(const float4*)&Bs[kk][tx * 8];
            float4 b1 = *(const float4*)&Bs[kk][tx * 8 + 4];
            float ar[8] = {a0.x, a0.y, a0.z, a0.w, a1.x, a1.y, a1.z, a1.w};
            float br[8] = {b0.x, b0.y, b0.z, b0.w, b1.x, b1.y, b1.z, b1.w};
#pragma unroll
            for (int i = 0; i < 8; i++)
#pragma unroll
                for (int j = 0; j < 8; j++) acc[i][j] += ar[i] * br[j];
        }
        __syncthreads();
    }

#pragma unroll
    for (int i = 0; i < 8; i++) {
        const int m = m0 + ty * 8 + i;
#pragma unroll
        for (int j = 0; j < 8; j += 4) {
            const int n = n0 + tx * 8 + j;
            float4 bb = *(const float4*)&bo[n];
            float4 v = make_float4(acc[i][j] + bb.x, acc[i][j+1] + bb.y,
                                   acc[i][j+2] + bb.z, acc[i][j+3] + bb.w);
            *(float4*)&Out[(size_t)m * EMB + n] = v;
        }
    }
}

// ---------------------------------------------------------------------------
// Attention v4 (inverted causal mask: attend only strictly-future keys).
// Same structure/math as the proven R13 kernel (double-buffered K/V, chunk-8
// online softmax carrying -1e9, last q-block sees all keys), but all heavy
// arithmetic in packed f32x2: q and acc live as 16 u64 pairs (regs ~150->~95
// => 3->5 blocks/SM), per-key instructions ~170 -> ~80. Elementwise FMA/mul
// are exact fp32; only the dot's summation order changes (pairwise + 1 add).
// ---------------------------------------------------------------------------
#define BQ  128
#define BKV 32

__global__ __launch_bounds__(BQ) void attn_kernel()
{
    const int bh = blockIdx.y;              // b*16 + h
    const int b  = bh >> 4;
    const int h  = bh & 15;
    const int q0 = blockIdx.x * BQ;
    const int t  = threadIdx.x;
    const int qrow = q0 + t;

    const float* Qb = g_q + (size_t)bh * S_LEN * HDIM;
    const float* Kb = g_k + (size_t)bh * S_LEN * HDIM;
    const float* Vb = g_v + (size_t)bh * S_LEN * HDIM;

    __shared__ float Ks[2][BKV * HDIM];     // 2 x 8KB
    __shared__ float Vs[2][BKV * HDIM];     // 2 x 8KB

    // 64 dims of q as 32 packed pairs
    u64p q2[16];
    const u64p* qp = (const u64p*)(Qb + (size_t)qrow * HDIM);
#pragma unroll
    for (int i = 0; i < 16; i++) {
        u64p a = qp[2 * i];
        u64p c = qp[2 * i + 1];
        q2[i] = a; (void)c;
    }
    // NOTE: HDIM=64 -> 32 pairs; hold all 32
    u64p q2b[16];
#pragma unroll
    for (int i = 0; i < 16; i++) q2b[i] = qp[16 + i];
#pragma unroll
    for (int i = 0; i < 16; i++) q2[i] = qp[i];

    u64p acc2[32];
#pragma unroll
    for (int i = 0; i < 32; i++) acc2[i] = 0ull;

    float mrun = -1e30f;
    float lrun = 0.f;
    const float sc_qk = 0.125f;             // 1/sqrt(64)

    const int ntiles = S_LEN / BKV;         // 64
    const int tstart = (blockIdx.x == gridDim.x - 1) ? 0 : (q0 / BKV);

    // Prologue: load tile tstart into buffer 0.
    {
        const float* kp = Kb + (size_t)tstart * BKV * HDIM;
        const float* vp = Vb + (size_t)tstart * BKV * HDIM;
        for (int i = t * 4; i < BKV * HDIM; i += BQ * 4) {
            *(float4*)(&Ks[0][i]) = *(const float4*)(kp + i);
            *(float4*)(&Vs[0][i]) = *(const float4*)(vp + i);
        }
    }
    __syncthreads();

    for (int kt = tstart; kt < ntiles; kt++) {
        const int buf = (kt - tstart) & 1;

        // Prefetch tile kt+1 into the other buffer (overlaps with compute).
        if (kt + 1 < ntiles) {
            const float* kp = Kb + (size_t)(kt + 1) * BKV * HDIM;
            const float* vp = Vb + (size_t)(kt + 1) * BKV * HDIM;
            for (int i = t * 4; i < BKV * HDIM; i += BQ * 4) {
                *(float4*)(&Ks[buf ^ 1][i]) = *(const float4*)(kp + i);
                *(float4*)(&Vs[buf ^ 1][i]) = *(const float4*)(vp + i);
            }
        }

#pragma unroll 1
        for (int jc = 0; jc < BKV; jc += 8) {
            float sc[8];
#pragma unroll
            for (int jj = 0; jj < 8; jj++) {
                const u64p* kp = (const u64p*)(&Ks[buf][(jc + jj) * HDIM]);
                u64p d0 = 0ull, d1 = 0ull;
#pragma unroll
                for (int i = 0; i < 16; i++) {
                    fma2(d0, q2[i],  kp[i]);
                    fma2(d1, q2b[i], kp[16 + i]);
                }
                float2 e0 = unpack2(d0);
                float2 e1 = unpack2(d1);
                const float sum = (e0.x + e0.y) + (e1.x + e1.y);
                const int kg = kt * BKV + jc + jj;
                sc[jj] = (kg > qrow) ? sum * sc_qk : -1e9f;
            }
            float cmax = sc[0];
#pragma unroll
            for (int jj = 1; jj < 8; jj++) cmax = fmaxf(cmax, sc[jj]);
            const float mnew = fmaxf(mrun, cmax);
            const float corr = __expf(mrun - mnew);
            lrun *= corr;
            const u64p cpk = pack2(corr, corr);
#pragma unroll
            for (int i = 0; i < 32; i++) mul2(acc2[i], acc2[i], cpk);
#pragma unroll
            for (int jj = 0; jj < 8; jj++) {
                const float p = __expf(sc[jj] - mnew);
                lrun += p;
                const u64p ppk = pack2(p, p);
                const u64p* vp = (const u64p*)(&Vs[buf][(jc + jj) * HDIM]);
#pragma unroll
                for (int i = 0; i < 32; i++) fma2(acc2[i], ppk, vp[i]);
            }
            mrun = mnew;
        }
        __syncthreads();
    }

    const float inv = 1.f / lrun;
    float* op = g_att + ((size_t)(b * S_LEN + qrow)) * EMB + h * HDIM;
#pragma unroll
    for (int i = 0; i < 16; i++) {
        float2 p0 = unpack2(acc2[2 * i]);
        float2 p1 = unpack2(acc2[2 * i + 1]);
        float4 v = make_float4(p0.x * inv, p0.y * inv, p1.x * inv, p1.y * inv);
        ((float4*)op)[i] = v;
    }
}

// ---------------------------------------------------------------------------
extern "C" void kernel_launch(void* const* d_in, const int* in_sizes, int n_in,
                              void* d_out, int out_size)
{
    const float* x  = (const float*)d_in[0];
    const float* wq = (const float*)d_in[1];
    const float* wk = (const float*)d_in[2];
    const float* wv = (const float*)d_in[3];
    const float* wo = (const float*)d_in[4];
    const float* bo = (const float*)d_in[5];
    float* out = (float*)d_out;

    // 1) QKV projections -> g_q/g_k/g_v in [b,h,s,d]
    {
        dim3 grid(EMB / BN, MROWS / BM, 3);
        qkv_gemm<<<grid, 256>>>(x, wq, wk, wv);
    }
    // 2) Attention -> g_att in [b,s,e]
    {
        dim3 grid(S_LEN / BQ, BATCH * NHEAD);
        attn_kernel<<<grid, BQ>>>();
    }
    // 3) Output projection + bias -> d_out
    {
        dim3 grid(EMB / BN, MROWS / BM);
        outproj_gemm<<<grid, 256>>>(wo, bo, out);
    }
}